// round 7
// baseline (speedup 1.0000x reference)
#include <cuda_runtime.h>
#include <cuda_fp16.h>
#include <math.h>

// Problem constants
#define BB 2
#define VV 180
#define RR 32
#define CC 512
#define NPIX 512
#define NROWS (BB*VV*RR)        // 11520
#define NQUADS (NROWS/4)        // 2880
#define PADL 107
#define NPADE 724               // padded entries per row
#define RT 4                    // r-images per bp block (1 quad)
#define YTN 8                   // y rows per bp block
#define PI_D 3.14159265358979323846
#define MAGICF 12582912.0f      // 1.5*2^23, float bits 0x4B400000

// ---------------- device globals (scratch; no runtime allocation allowed) ----------------
__device__ __align__(16) float  g_h[512];                     // ramp conv kernel
__device__ __align__(16) float2 g_cs[VV];                     // (cos, sin) per angle
// quad-interleaved padded rows: 16B entry = (mid2(r0,r1), d2(r0,r1), mid2(r2,r3), d2(r2,r3))
__device__ __align__(16) uint4  g_quad[(size_t)NQUADS * NPADE];   // ~33MB

// ---------------- packed f32x2 helpers (Blackwell) --------------------------------------
__device__ __forceinline__ unsigned long long pk2(float lo, float hi) {
    unsigned long long r; asm("mov.b64 %0, {%1,%2};" : "=l"(r) : "f"(lo), "f"(hi)); return r;
}
__device__ __forceinline__ unsigned long long fadd2(unsigned long long a, unsigned long long b) {
    unsigned long long r; asm("add.rn.f32x2 %0, %1, %2;" : "=l"(r) : "l"(a), "l"(b)); return r;
}
__device__ __forceinline__ unsigned long long ffma2p(unsigned long long a, unsigned long long b,
                                                     unsigned long long c) {
    unsigned long long r; asm("fma.rn.f32x2 %0, %1, %2, %3;" : "=l"(r) : "l"(a), "l"(b), "l"(c)); return r;
}

// ---------------- setup: h[j] = (1/512) sum_m ramp[m] cos(2 pi m j / 512); cs table -----
__global__ void setup_kernel() {
    __shared__ double part[128];
    int tid = threadIdx.x;
    if (blockIdx.x == 512) {
        for (int v = tid; v < VV; v += 128) {
            double th = PI_D * (double)v / (double)VV;
            g_cs[v] = make_float2((float)cos(th), (float)sin(th));
        }
        return;
    }
    int j = blockIdx.x;  // 0..511
    double s = 0.0;
    for (int m = tid; m < 512; m += 128) {
        double f = (m < 256) ? (double)m / 512.0 : (double)(m - 512) / 512.0;
        s += 2.0 * fabs(f) * cos(2.0 * PI_D * (double)m * (double)j / 512.0);
    }
    part[tid] = s;
    __syncthreads();
    for (int o = 64; o > 0; o >>= 1) {
        if (tid < o) part[tid] += part[tid + o];
        __syncthreads();
    }
    if (tid == 0) g_h[j] = (float)(part[0] / 512.0);
}

// ---------------- filter: 4 rows/block, circular conv (sliding reuse) + quad write -----
// 2880 blocks x 512 threads; group g = row within quad, 128 threads per row,
// 4 consecutive outputs per thread. rb(d0+4)==ra(d0) -> 1 data LDS.128 per step.
__global__ void __launch_bounds__(512) filter_kernel(const float* __restrict__ sino) {
    __shared__ __align__(16) float srow2[4][1024];  // each row duplicated (mod-512 windows)
    __shared__ __align__(16) float sh[512];         // conv kernel
    __shared__ __align__(16) float sF[4][512];      // filtered outputs

    int quad = blockIdx.x;             // 0..2879
    int g   = threadIdx.x >> 7;        // 0..3 : row within quad
    int tid = threadIdx.x & 127;

    const float4* rp = (const float4*)(sino + (size_t)(quad * 4 + g) * CC);
    float4 rv4 = rp[tid];
    ((float4*)srow2[g])[tid]       = rv4;
    ((float4*)srow2[g])[tid + 128] = rv4;           // duplicate
    if (g == 0) ((float4*)sh)[tid] = ((const float4*)g_h)[tid];
    __syncthreads();

    const float* rw = srow2[g];
    int c0 = tid * 4;
    float a0 = 0.f, a1 = 0.f, a2 = 0.f, a3 = 0.f;

    float4 rb = *(const float4*)&rw[c0 + 512];      // rb for d0=0
    #pragma unroll 4
    for (int d0 = 0; d0 < 512; d0 += 4) {
        float4 hv = *(const float4*)&sh[d0];        // warp-broadcast
        float4 ra = *(const float4*)&rw[c0 - d0 + 508];
        a0 = fmaf(hv.x, rb.x, a0); a0 = fmaf(hv.y, ra.w, a0); a0 = fmaf(hv.z, ra.z, a0); a0 = fmaf(hv.w, ra.y, a0);
        a1 = fmaf(hv.x, rb.y, a1); a1 = fmaf(hv.y, rb.x, a1); a1 = fmaf(hv.z, ra.w, a1); a1 = fmaf(hv.w, ra.z, a1);
        a2 = fmaf(hv.x, rb.z, a2); a2 = fmaf(hv.y, rb.y, a2); a2 = fmaf(hv.z, rb.x, a2); a2 = fmaf(hv.w, ra.w, a2);
        a3 = fmaf(hv.x, rb.w, a3); a3 = fmaf(hv.y, rb.z, a3); a3 = fmaf(hv.z, rb.y, a3); a3 = fmaf(hv.w, rb.x, a3);
        rb = ra;                                    // sliding-window reuse
    }
    *(float4*)&sF[g][c0] = make_float4(a0, a1, a2, a3);
    __syncthreads();

    // quad write: entry[j] = (mid2(r0,r1), d2(r0,r1), mid2(r2,r3), d2(r2,r3))
    uint4* dst = g_quad + (size_t)quad * NPADE;
    for (int j = threadIdx.x; j < NPADE; j += 512) {
        int ia = j - PADL;       ia = ia < 0 ? 0 : (ia > 511 ? 511 : ia);
        int ib = j - (PADL - 1); ib = ib < 0 ? 0 : (ib > 511 ? 511 : ib);
        float f0a = sF[0][ia], f0b = sF[0][ib];
        float f1a = sF[1][ia], f1b = sF[1][ib];
        float f2a = sF[2][ia], f2b = sF[2][ib];
        float f3a = sF[3][ia], f3b = sF[3][ib];
        __half2 m01 = __floats2half2_rn(0.5f * (f0a + f0b), 0.5f * (f1a + f1b));
        __half2 d01 = __floats2half2_rn(f0b - f0a, f1b - f1a);
        __half2 m23 = __floats2half2_rn(0.5f * (f2a + f2b), 0.5f * (f3a + f3b));
        __half2 d23 = __floats2half2_rn(f2b - f2a, f3b - f3a);
        uint4 e;
        e.x = *(unsigned int*)&m01; e.y = *(unsigned int*)&d01;
        e.z = *(unsigned int*)&m23; e.w = *(unsigned int*)&d23;
        dst[j] = e;
    }
}

// ---------------- backprojection --------------------------------------------------------
// 1024 blocks: (b, quad rq, 8-y slab) x 512 threads (one x each).
// i0 = round(t-0.5) via float-magic; signed w' = (t-0.5) - i0; val = mid + w'*d.
// One LDS.128 per j covers all 4 r-samples. Packed f32x2 index math + accumulate.
__global__ void __launch_bounds__(512, 2) bp_kernel(float* __restrict__ out) {
    __shared__ __align__(16) uint4 sbuf[2][NPADE];  // 2 x 11.6KB
    __shared__ float2 scs[VV];

    int tid  = threadIdx.x;
    int blk  = blockIdx.x;
    int slab = blk & 63;              // NPIX/YTN = 64
    int rq   = (blk >> 6) & 7;        // RR/RT = 8
    int b    = blk >> 9;

    if (tid < VV) scs[tid] = g_cs[tid];

    // quad chunk base: quad index (b*VV + v)*8 + rq
    const uint4* basep = g_quad + ((size_t)(b * VV) * 8 + rq) * NPADE;
    const size_t vstr  = (size_t)8 * NPADE;   // uint4 per v step

    bool l2 = tid < (NPADE - 512);    // 212 threads load a second uint4
    uint4 p0 = basep[tid];
    uint4 p1; if (l2) p1 = basep[tid + 512];
    sbuf[0][tid] = p0;
    if (l2) sbuf[0][tid + 512] = p1;
    p0 = basep[vstr + tid];
    if (l2) p1 = basep[vstr + tid + 512];
    __syncthreads();

    // 32-bit smem addresses for magic-biased indexed loads
    unsigned int sb32;
    asm("{ .reg .u64 t; cvta.to.shared.u64 t, %1; cvt.u32.u64 %0, t; }"
        : "=r"(sb32) : "l"((void*)&sbuf[0][0]));
    // addr = ts_bits*16 + cbase, where ts_bits = 0x4B400000 + i0 (wraps mod 2^32)
    unsigned int cb0 = sb32 - 0xB4000000u;                    // 0x4B400000*16 mod 2^32
    unsigned int cb1 = cb0 + (unsigned int)(NPADE * 16);

    float xp = (float)tid - 255.5f;
    float yb = (float)(slab * YTN) - 255.5f;

    const unsigned long long magic2    = pk2(MAGICF, MAGICF);
    const unsigned long long negmagic2 = pk2(-MAGICF, -MAGICF);
    const unsigned long long negone2   = pk2(-1.0f, -1.0f);

    unsigned long long acc2[2][YTN];
    #pragma unroll
    for (int pp = 0; pp < 2; pp++)
        #pragma unroll
        for (int j = 0; j < YTN; j++) acc2[pp][j] = 0ull;

    for (int v = 0; v < VV; v++) {
        if (v + 1 < VV) {   // store prefetched v+1 into the other buffer
            uint4* nb = sbuf[(v + 1) & 1];
            nb[tid] = p0;
            if (l2) nb[tid + 512] = p1;
        }
        unsigned int cbase = (v & 1) ? cb1 : cb0;
        float2 cs = scs[v];
        // t' = t - 0.5 for j=0; packed pair (j, j+1)
        float tp0 = fmaf(xp, cs.x, fmaf(yb, cs.y, 255.5f + (float)PADL - 0.5f));
        unsigned long long t2    = pk2(tp0, tp0 + cs.y);
        unsigned long long step2 = pk2(cs.y + cs.y, cs.y + cs.y);

        #pragma unroll
        for (int jp = 0; jp < YTN / 2; jp++) {
            unsigned long long ts2  = fadd2(t2, magic2);        // biased round(t')
            unsigned long long i0f2 = fadd2(ts2, negmagic2);    // exact i0 as float
            unsigned long long w2   = ffma2p(i0f2, negone2, t2); // w' = t' - i0  in [-0.5,0.5]
            t2 = fadd2(t2, step2);

            unsigned int tsl, tsh; float wl, wh;
            asm("mov.b64 {%0,%1}, %2;" : "=r"(tsl), "=r"(tsh) : "l"(ts2));
            asm("mov.b64 {%0,%1}, %2;" : "=f"(wl),  "=f"(wh)  : "l"(w2));

            #pragma unroll
            for (int hh = 0; hh < 2; hh++) {
                int j = jp * 2 + hh;
                unsigned int addr = (hh ? tsh : tsl) * 16u + cbase;
                unsigned int ex, ey, ez, ew;
                asm("ld.shared.v4.b32 {%0,%1,%2,%3}, [%4];"
                    : "=r"(ex), "=r"(ey), "=r"(ez), "=r"(ew) : "r"(addr));
                unsigned int whb;
                float wv = hh ? wh : wl;
                asm("cvt.rn.f16x2.f32 %0, %1, %1;" : "=r"(whb) : "f"(wv)); // broadcast half2
                __half2 w2h = *(__half2*)&whb;
                __half2 v0 = __hfma2(w2h, *(__half2*)&ey, *(__half2*)&ex); // rows 0,1
                __half2 v1 = __hfma2(w2h, *(__half2*)&ew, *(__half2*)&ez); // rows 2,3
                float2 f0 = __half22float2(v0);
                float2 f1 = __half22float2(v1);
                asm("{ .reg .b64 t; mov.b64 t, {%1,%2}; add.rn.f32x2 %0, %0, t; }"
                    : "+l"(acc2[0][j]) : "f"(f0.x), "f"(f0.y));
                asm("{ .reg .b64 t; mov.b64 t, {%1,%2}; add.rn.f32x2 %0, %0, t; }"
                    : "+l"(acc2[1][j]) : "f"(f1.x), "f"(f1.y));
            }
        }

        if (v + 2 < VV) {   // prefetch v+2 (overlaps next iteration's compute)
            p0 = basep[(size_t)(v + 2) * vstr + tid];
            if (l2) p1 = basep[(size_t)(v + 2) * vstr + tid + 512];
        }
        __syncthreads();
    }

    const float scale = (float)(PI_D / (double)VV);
    int y0 = slab * YTN;
    #pragma unroll
    for (int pp = 0; pp < 2; pp++) {
        #pragma unroll
        for (int lane = 0; lane < 2; lane++) {
            int r = rq * 4 + pp * 2 + lane;
            size_t obase = (((size_t)(b * RR + r)) * NPIX + y0) * NPIX + tid;
            #pragma unroll
            for (int j = 0; j < YTN; j++) {
                float flo, fhi;
                asm("mov.b64 {%0,%1}, %2;" : "=f"(flo), "=f"(fhi) : "l"(acc2[pp][j]));
                float val = (lane ? fhi : flo) * scale;
                out[obase + (size_t)j * NPIX] = val > 0.f ? val : 0.f;
            }
        }
    }
}

// ---------------- launch ----------------------------------------------------------------
extern "C" void kernel_launch(void* const* d_in, const int* in_sizes, int n_in,
                              void* d_out, int out_size) {
    const float* sino = (const float*)d_in[0];
    float* out = (float*)d_out;
    (void)in_sizes; (void)n_in; (void)out_size;

    setup_kernel<<<513, 128>>>();
    filter_kernel<<<NQUADS, 512>>>(sino);
    bp_kernel<<<BB * (RR / RT) * (NPIX / YTN), 512>>>(out);
}

// round 8
// speedup vs baseline: 1.1116x; 1.1116x over previous
#include <cuda_runtime.h>
#include <cuda_fp16.h>
#include <math.h>

// Problem constants
#define BB 2
#define VV 180
#define RR 32
#define CC 512
#define NPIX 512
#define NROWS (BB*VV*RR)        // 11520
#define NQUADS (NROWS/4)        // 2880
#define PADL 107
#define NPADE 724               // padded entries per row
#define RT 4                    // r-images per bp block (1 quad)
#define YTN 8                   // y rows per bp block
#define PI_D 3.14159265358979323846
#define MAGICF 12582912.0f      // 1.5*2^23, float bits 0x4B400000

// ---------------- device globals (scratch; no runtime allocation allowed) ----------------
// quad-interleaved padded rows: 16B entry = (mid2(r0,r1), d2(r0,r1), mid2(r2,r3), d2(r2,r3))
__device__ __align__(16) uint4 g_quad[(size_t)NQUADS * NPADE];   // ~33MB

// ---------------- filter: closed-form Ram-Lak, parity-split conv, quad write -----------
// h[0]=1/2, h[even]=0, h[odd j]=-(2/N^2)/sin^2(pi j/N). Even/odd outputs each reduce to a
// 256-tap circular conv against the opposite-parity half-row, + 0.5*own sample.
// 2880 blocks x 512 threads; g=row in quad (tid>>7), 128 threads/row:
// p=(lt>>6) parity handled, q=lt&63 -> 4 consecutive outputs of that parity.
__global__ void __launch_bounds__(512) filter_kernel(const float* __restrict__ sino) {
    __shared__ __align__(16) float sE[4][512];   // even samples, duplicated halves
    __shared__ __align__(16) float sO[4][512];   // odd samples, duplicated halves
    __shared__ __align__(16) float sh[256];      // h_k = h[2k+1]
    __shared__ __align__(16) float sF[4][512];   // filtered outputs

    int quad = blockIdx.x;             // 0..2879
    int g   = threadIdx.x >> 7;        // row within quad
    int lt  = threadIdx.x & 127;

    // load row, split parity, duplicate
    const float4* rp = (const float4*)(sino + (size_t)(quad * 4 + g) * CC);
    float4 rv = rp[lt];
    int e0i = lt * 2;
    *(float2*)&sE[g][e0i]       = make_float2(rv.x, rv.z);
    *(float2*)&sE[g][e0i + 256] = make_float2(rv.x, rv.z);
    *(float2*)&sO[g][e0i]       = make_float2(rv.y, rv.w);
    *(float2*)&sO[g][e0i + 256] = make_float2(rv.y, rv.w);

    // closed-form odd taps
    if (threadIdx.x < 256) {
        int k = threadIdx.x;
        float s = sinf((float)(2 * k + 1) * (float)(PI_D / 512.0));
        sh[k] = -7.62939453125e-6f / (s * s);    // -(2/512^2)/sin^2
    }
    __syncthreads();

    int p  = lt >> 6;                  // 0: even outputs, 1: odd outputs
    int q  = lt & 63;
    int o0 = q * 4;                    // output index within the 256 half

    const float* part = p ? sE[g] : sO[g];   // conv input (opposite parity)
    const float* own  = p ? sO[g] : sE[g];   // 0.5 term (same parity)

    float a0 = 0.f, a1 = 0.f, a2 = 0.f, a3 = 0.f;
    float4 rb = *(const float4*)&part[o0 + 256];   // rb for k0=0
    if (p == 0) {
        // even: idx = o0 + i - 1 - k ; offset(i,j) = i-j+3
        #pragma unroll 4
        for (int k0 = 0; k0 < 256; k0 += 4) {
            float4 hv = *(const float4*)&sh[k0];
            float4 ra = *(const float4*)&part[o0 - k0 + 252];
            a0 = fmaf(hv.x, ra.w, a0); a0 = fmaf(hv.y, ra.z, a0); a0 = fmaf(hv.z, ra.y, a0); a0 = fmaf(hv.w, ra.x, a0);
            a1 = fmaf(hv.x, rb.x, a1); a1 = fmaf(hv.y, ra.w, a1); a1 = fmaf(hv.z, ra.z, a1); a1 = fmaf(hv.w, ra.y, a1);
            a2 = fmaf(hv.x, rb.y, a2); a2 = fmaf(hv.y, rb.x, a2); a2 = fmaf(hv.z, ra.w, a2); a2 = fmaf(hv.w, ra.z, a2);
            a3 = fmaf(hv.x, rb.z, a3); a3 = fmaf(hv.y, rb.y, a3); a3 = fmaf(hv.z, rb.x, a3); a3 = fmaf(hv.w, ra.w, a3);
            rb = ra;
        }
    } else {
        // odd: idx = o0 + i - k ; offset(i,j) = i-j+4
        #pragma unroll 4
        for (int k0 = 0; k0 < 256; k0 += 4) {
            float4 hv = *(const float4*)&sh[k0];
            float4 ra = *(const float4*)&part[o0 - k0 + 252];
            a0 = fmaf(hv.x, rb.x, a0); a0 = fmaf(hv.y, ra.w, a0); a0 = fmaf(hv.z, ra.z, a0); a0 = fmaf(hv.w, ra.y, a0);
            a1 = fmaf(hv.x, rb.y, a1); a1 = fmaf(hv.y, rb.x, a1); a1 = fmaf(hv.z, ra.w, a1); a1 = fmaf(hv.w, ra.z, a1);
            a2 = fmaf(hv.x, rb.z, a2); a2 = fmaf(hv.y, rb.y, a2); a2 = fmaf(hv.z, rb.x, a2); a2 = fmaf(hv.w, ra.w, a2);
            a3 = fmaf(hv.x, rb.w, a3); a3 = fmaf(hv.y, rb.z, a3); a3 = fmaf(hv.z, rb.y, a3); a3 = fmaf(hv.w, rb.x, a3);
            rb = ra;
        }
    }
    int outbase = 2 * o0 + p;          // stride-2 positions of this parity
    sF[g][outbase + 0] = fmaf(0.5f, own[o0 + 0], a0);
    sF[g][outbase + 2] = fmaf(0.5f, own[o0 + 1], a1);
    sF[g][outbase + 4] = fmaf(0.5f, own[o0 + 2], a2);
    sF[g][outbase + 6] = fmaf(0.5f, own[o0 + 3], a3);
    __syncthreads();

    // quad write: entry[j] = (mid2(r0,r1), d2(r0,r1), mid2(r2,r3), d2(r2,r3))
    uint4* dst = g_quad + (size_t)quad * NPADE;
    for (int j = threadIdx.x; j < NPADE; j += 512) {
        int ia = j - PADL;       ia = ia < 0 ? 0 : (ia > 511 ? 511 : ia);
        int ib = j - (PADL - 1); ib = ib < 0 ? 0 : (ib > 511 ? 511 : ib);
        float f0a = sF[0][ia], f0b = sF[0][ib];
        float f1a = sF[1][ia], f1b = sF[1][ib];
        float f2a = sF[2][ia], f2b = sF[2][ib];
        float f3a = sF[3][ia], f3b = sF[3][ib];
        __half2 m01 = __floats2half2_rn(0.5f * (f0a + f0b), 0.5f * (f1a + f1b));
        __half2 d01 = __floats2half2_rn(f0b - f0a, f1b - f1a);
        __half2 m23 = __floats2half2_rn(0.5f * (f2a + f2b), 0.5f * (f3a + f3b));
        __half2 d23 = __floats2half2_rn(f2b - f2a, f3b - f3a);
        uint4 e;
        e.x = *(unsigned int*)&m01; e.y = *(unsigned int*)&d01;
        e.z = *(unsigned int*)&m23; e.w = *(unsigned int*)&d23;
        dst[j] = e;
    }
}

// ---------------- backprojection --------------------------------------------------------
// 1024 blocks: (b, quad rq, 8-y slab) x 512 threads (one x each).
// i0 = round(t-0.5) via float-magic (plain C); signed w' in [-0.5,0.5]; val = mid + w'*d.
// One LDS.128 per j covers all 4 r-samples; scalar f32 accumulators.
__global__ void __launch_bounds__(512, 2) bp_kernel(float* __restrict__ out) {
    __shared__ __align__(16) uint4 sbuf[2][NPADE];  // 2 x 11.6KB
    __shared__ float2 scs[VV];

    int tid  = threadIdx.x;
    int blk  = blockIdx.x;
    int slab = blk & 63;              // NPIX/YTN = 64
    int rq   = (blk >> 6) & 7;        // RR/RT = 8
    int b    = blk >> 9;

    if (tid < VV) {
        float th = (float)((double)tid * (PI_D / (double)VV));
        float s, c;
        sincosf(th, &s, &c);
        scs[tid] = make_float2(c, s);
    }

    // quad chunk base: quad index (b*VV + v)*8 + rq
    const uint4* basep = g_quad + ((size_t)(b * VV) * 8 + rq) * NPADE;
    const size_t vstr  = (size_t)8 * NPADE;   // uint4 per v step

    bool l2 = tid < (NPADE - 512);    // 212 threads load a second uint4
    uint4 p0 = basep[tid];
    uint4 p1; if (l2) p1 = basep[tid + 512];
    sbuf[0][tid] = p0;
    if (l2) sbuf[0][tid + 512] = p1;
    p0 = basep[vstr + tid];
    if (l2) p1 = basep[vstr + tid + 512];
    __syncthreads();

    // 32-bit smem base for magic-biased indexed loads:
    // addr = float_bits(t'+MAGIC)*16 + cbase, cbase = smem(sbuf) - 0x4B400000*16 (mod 2^32)
    unsigned int sb32;
    asm("{ .reg .u64 t; cvta.to.shared.u64 t, %1; cvt.u32.u64 %0, t; }"
        : "=r"(sb32) : "l"((void*)&sbuf[0][0]));
    unsigned int cb0 = sb32 - 0xB4000000u;
    unsigned int cb1 = cb0 + (unsigned int)(NPADE * 16);

    float xp = (float)tid - 255.5f;
    float yb = (float)(slab * YTN) - 255.5f;

    float acc[RT][YTN];
    #pragma unroll
    for (int rr = 0; rr < RT; rr++)
        #pragma unroll
        for (int j = 0; j < YTN; j++) acc[rr][j] = 0.f;

    for (int v = 0; v < VV; v++) {
        if (v + 1 < VV) {   // store prefetched v+1 into the other buffer
            uint4* nb = sbuf[(v + 1) & 1];
            nb[tid] = p0;
            if (l2) nb[tid + 512] = p1;
        }
        unsigned int cbase = (v & 1) ? cb1 : cb0;
        float2 cs = scs[v];
        // t' = t - 0.5 at j=0
        float t0p = fmaf(xp, cs.x, fmaf(yb, cs.y, 255.5f + (float)PADL - 0.5f));
        #pragma unroll
        for (int j = 0; j < YTN; j++) {
            float tp  = fmaf((float)j, cs.y, t0p);
            float ts  = __fadd_rn(tp, MAGICF);      // biased round(t')
            float i0f = __fadd_rn(ts, -MAGICF);     // exact i0 as float
            float w   = __fadd_rn(tp, -i0f);        // w' in [-0.5, 0.5]
            unsigned int addr = __float_as_uint(ts) * 16u + cbase;
            unsigned int ex, ey, ez, ew;
            asm("ld.shared.v4.b32 {%0,%1,%2,%3}, [%4];"
                : "=r"(ex), "=r"(ey), "=r"(ez), "=r"(ew) : "r"(addr));
            unsigned int wb;
            asm("cvt.rn.f16x2.f32 %0, %1, %1;" : "=r"(wb) : "f"(w));   // half2(w, w)
            __half2 w2h = *(__half2*)&wb;
            __half2 v0 = __hfma2(w2h, *(__half2*)&ey, *(__half2*)&ex); // rows 0,1
            __half2 v1 = __hfma2(w2h, *(__half2*)&ew, *(__half2*)&ez); // rows 2,3
            acc[0][j] += __low2float(v0);
            acc[1][j] += __high2float(v0);
            acc[2][j] += __low2float(v1);
            acc[3][j] += __high2float(v1);
        }
        if (v + 2 < VV) {   // prefetch v+2 (overlaps next iteration's compute)
            p0 = basep[(size_t)(v + 2) * vstr + tid];
            if (l2) p1 = basep[(size_t)(v + 2) * vstr + tid + 512];
        }
        __syncthreads();
    }

    const float scale = (float)(PI_D / (double)VV);
    int y0 = slab * YTN;
    #pragma unroll
    for (int rr = 0; rr < RT; rr++) {
        size_t obase = (((size_t)(b * RR + rq * RT + rr)) * NPIX + y0) * NPIX + tid;
        #pragma unroll
        for (int j = 0; j < YTN; j++) {
            float val = acc[rr][j] * scale;
            out[obase + (size_t)j * NPIX] = val > 0.f ? val : 0.f;
        }
    }
}

// ---------------- launch ----------------------------------------------------------------
extern "C" void kernel_launch(void* const* d_in, const int* in_sizes, int n_in,
                              void* d_out, int out_size) {
    const float* sino = (const float*)d_in[0];
    float* out = (float*)d_out;
    (void)in_sizes; (void)n_in; (void)out_size;

    filter_kernel<<<NQUADS, 512>>>(sino);
    bp_kernel<<<BB * (RR / RT) * (NPIX / YTN), 512>>>(out);
}

// round 9
// speedup vs baseline: 1.3315x; 1.1978x over previous
#include <cuda_runtime.h>
#include <cuda_fp16.h>
#include <math.h>

// Problem constants
#define BB 2
#define VV 180
#define RR 32
#define CC 512
#define NPIX 512
#define NROWS (BB*VV*RR)        // 11520
#define NQUADS (NROWS/4)        // 2880
#define PADL 107
#define NPADE 724               // padded entries per row
#define RT 4                    // r-images per bp block (1 quad)
#define YTN 8                   // y rows per bp block
#define VCHUNK 6                // angles per half2-accumulation chunk (multiple of 3)
#define PI_D 3.14159265358979323846
#define MAGICF 12582912.0f      // 1.5*2^23, float bits 0x4B400000

// ---------------- device globals (scratch; no runtime allocation allowed) ----------------
// quad-interleaved padded rows: 16B entry = (mid2(r0,r1), d2(r0,r1), mid2(r2,r3), d2(r2,r3))
__device__ __align__(16) uint4 g_quad[(size_t)NQUADS * NPADE];   // ~33MB

// ---------------- filter: closed-form Ram-Lak, parity-split conv, quad write -----------
// h[0]=1/2, h[even]=0, h[odd j]=-(2/N^2)/sin^2(pi j/N). Even/odd outputs each reduce to a
// 256-tap circular conv against the opposite-parity half-row, + 0.5*own sample.
__global__ void __launch_bounds__(512) filter_kernel(const float* __restrict__ sino) {
    __shared__ __align__(16) float sE[4][512];   // even samples, duplicated halves
    __shared__ __align__(16) float sO[4][512];   // odd samples, duplicated halves
    __shared__ __align__(16) float sh[256];      // h_k = h[2k+1]
    __shared__ __align__(16) float sF[4][512];   // filtered outputs

    int quad = blockIdx.x;             // 0..2879
    int g   = threadIdx.x >> 7;        // row within quad
    int lt  = threadIdx.x & 127;

    const float4* rp = (const float4*)(sino + (size_t)(quad * 4 + g) * CC);
    float4 rv = rp[lt];
    int e0i = lt * 2;
    *(float2*)&sE[g][e0i]       = make_float2(rv.x, rv.z);
    *(float2*)&sE[g][e0i + 256] = make_float2(rv.x, rv.z);
    *(float2*)&sO[g][e0i]       = make_float2(rv.y, rv.w);
    *(float2*)&sO[g][e0i + 256] = make_float2(rv.y, rv.w);

    if (threadIdx.x < 256) {
        int k = threadIdx.x;
        float s = sinf((float)(2 * k + 1) * (float)(PI_D / 512.0));
        sh[k] = -7.62939453125e-6f / (s * s);    // -(2/512^2)/sin^2
    }
    __syncthreads();

    int p  = lt >> 6;                  // 0: even outputs, 1: odd outputs
    int q  = lt & 63;
    int o0 = q * 4;

    const float* part = p ? sE[g] : sO[g];
    const float* own  = p ? sO[g] : sE[g];

    float a0 = 0.f, a1 = 0.f, a2 = 0.f, a3 = 0.f;
    float4 rb = *(const float4*)&part[o0 + 256];
    if (p == 0) {
        #pragma unroll 4
        for (int k0 = 0; k0 < 256; k0 += 4) {
            float4 hv = *(const float4*)&sh[k0];
            float4 ra = *(const float4*)&part[o0 - k0 + 252];
            a0 = fmaf(hv.x, ra.w, a0); a0 = fmaf(hv.y, ra.z, a0); a0 = fmaf(hv.z, ra.y, a0); a0 = fmaf(hv.w, ra.x, a0);
            a1 = fmaf(hv.x, rb.x, a1); a1 = fmaf(hv.y, ra.w, a1); a1 = fmaf(hv.z, ra.z, a1); a1 = fmaf(hv.w, ra.y, a1);
            a2 = fmaf(hv.x, rb.y, a2); a2 = fmaf(hv.y, rb.x, a2); a2 = fmaf(hv.z, ra.w, a2); a2 = fmaf(hv.w, ra.z, a2);
            a3 = fmaf(hv.x, rb.z, a3); a3 = fmaf(hv.y, rb.y, a3); a3 = fmaf(hv.z, rb.x, a3); a3 = fmaf(hv.w, ra.w, a3);
            rb = ra;
        }
    } else {
        #pragma unroll 4
        for (int k0 = 0; k0 < 256; k0 += 4) {
            float4 hv = *(const float4*)&sh[k0];
            float4 ra = *(const float4*)&part[o0 - k0 + 252];
            a0 = fmaf(hv.x, rb.x, a0); a0 = fmaf(hv.y, ra.w, a0); a0 = fmaf(hv.z, ra.z, a0); a0 = fmaf(hv.w, ra.y, a0);
            a1 = fmaf(hv.x, rb.y, a1); a1 = fmaf(hv.y, rb.x, a1); a1 = fmaf(hv.z, ra.w, a1); a1 = fmaf(hv.w, ra.z, a1);
            a2 = fmaf(hv.x, rb.z, a2); a2 = fmaf(hv.y, rb.y, a2); a2 = fmaf(hv.z, rb.x, a2); a2 = fmaf(hv.w, ra.w, a2);
            a3 = fmaf(hv.x, rb.w, a3); a3 = fmaf(hv.y, rb.z, a3); a3 = fmaf(hv.z, rb.y, a3); a3 = fmaf(hv.w, rb.x, a3);
            rb = ra;
        }
    }
    int outbase = 2 * o0 + p;
    sF[g][outbase + 0] = fmaf(0.5f, own[o0 + 0], a0);
    sF[g][outbase + 2] = fmaf(0.5f, own[o0 + 1], a1);
    sF[g][outbase + 4] = fmaf(0.5f, own[o0 + 2], a2);
    sF[g][outbase + 6] = fmaf(0.5f, own[o0 + 3], a3);
    __syncthreads();

    uint4* dst = g_quad + (size_t)quad * NPADE;
    for (int j = threadIdx.x; j < NPADE; j += 512) {
        int ia = j - PADL;       ia = ia < 0 ? 0 : (ia > 511 ? 511 : ia);
        int ib = j - (PADL - 1); ib = ib < 0 ? 0 : (ib > 511 ? 511 : ib);
        float f0a = sF[0][ia], f0b = sF[0][ib];
        float f1a = sF[1][ia], f1b = sF[1][ib];
        float f2a = sF[2][ia], f2b = sF[2][ib];
        float f3a = sF[3][ia], f3b = sF[3][ib];
        __half2 m01 = __floats2half2_rn(0.5f * (f0a + f0b), 0.5f * (f1a + f1b));
        __half2 d01 = __floats2half2_rn(f0b - f0a, f1b - f1a);
        __half2 m23 = __floats2half2_rn(0.5f * (f2a + f2b), 0.5f * (f3a + f3b));
        __half2 d23 = __floats2half2_rn(f2b - f2a, f3b - f3a);
        uint4 e;
        e.x = *(unsigned int*)&m01; e.y = *(unsigned int*)&d01;
        e.z = *(unsigned int*)&m23; e.w = *(unsigned int*)&d23;
        dst[j] = e;
    }
}

// ---------------- cp.async helpers ------------------------------------------------------
__device__ __forceinline__ void cp16(unsigned int sdst, const void* gsrc) {
    asm volatile("cp.async.cg.shared.global [%0], [%1], 16;" :: "r"(sdst), "l"(gsrc));
}
__device__ __forceinline__ void cp_commit() { asm volatile("cp.async.commit_group;"); }
__device__ __forceinline__ void cp_wait1()  { asm volatile("cp.async.wait_group 1;"); }
__device__ __forceinline__ void cp_wait0()  { asm volatile("cp.async.wait_group 0;"); }

// ---------------- backprojection --------------------------------------------------------
// 1024 blocks: (b, quad rq, 8-y slab) x 512 threads (one x each).
// i0 = round(t-0.5) via float-magic; signed w' in [-0.5,0.5]; val = mid + w'*d.
// One LDS.128/j covers 4 r-samples; HADD2 chunk accumulation, f32 flush every 6 angles.
// Staging: cp.async into 3 smem buffers, one __syncthreads per angle.
#define BUFU4 NPADE
#define BUFB  (NPADE * 16)
__global__ void __launch_bounds__(512, 2) bp_kernel(float* __restrict__ out) {
    __shared__ __align__(16) uint4 sbuf[3][BUFU4];   // 3 x 11.6KB
    __shared__ float2 scs[VV];

    int tid  = threadIdx.x;
    int blk  = blockIdx.x;
    int slab = blk & 63;              // NPIX/YTN = 64
    int rq   = (blk >> 6) & 7;        // RR/RT = 8
    int b    = blk >> 9;

    if (tid < VV) {
        float th = (float)((double)tid * (PI_D / (double)VV));
        float s, c;
        sincosf(th, &s, &c);
        scs[tid] = make_float2(c, s);
    }

    // gmem source: quad index (b*VV + v)*8 + rq ; per-v stride 8*NPADE uint4
    const uint4* gbase = g_quad + ((size_t)(b * VV) * 8 + rq) * NPADE + tid;
    const bool   l2    = tid < (NPADE - 512);

    // smem dst/base addresses (32-bit shared window)
    unsigned int sb32;
    asm("{ .reg .u64 t; cvta.to.shared.u64 t, %1; cvt.u32.u64 %0, t; }"
        : "=r"(sb32) : "l"((void*)&sbuf[0][0]));
    unsigned int sdst = sb32 + (unsigned int)tid * 16u;
    // gather base: addr = float_bits(t'+MAGIC)*16 + cbase
    unsigned int cb = sb32 - 0xB4000000u;

    // prologue: stage v=0 -> buf0, v=1 -> buf1
    cp16(sdst, gbase);
    if (l2) cp16(sdst + 8192u, gbase + 512);
    cp_commit();
    cp16(sdst + BUFB, gbase + (size_t)8 * NPADE);
    if (l2) cp16(sdst + BUFB + 8192u, gbase + (size_t)8 * NPADE + 512);
    cp_commit();

    float xp = (float)tid - 255.5f;
    float yb = (float)(slab * YTN) - 255.5f;

    float acc[RT][YTN];
    #pragma unroll
    for (int rr = 0; rr < RT; rr++)
        #pragma unroll
        for (int j = 0; j < YTN; j++) acc[rr][j] = 0.f;

    for (int vc = 0; vc < VV / VCHUNK; vc++) {
        __half2 h01[YTN], h23[YTN];
        #pragma unroll
        for (int j = 0; j < YTN; j++) {
            h01[j] = __float2half2_rn(0.f);
            h23[j] = __float2half2_rn(0.f);
        }
        #pragma unroll
        for (int vi = 0; vi < VCHUNK; vi++) {
            int v = vc * VCHUNK + vi;
            cp_wait1();
            __syncthreads();
            // issue stage for v+2 into buf[(v+2)%3] (clamped at VV-1; harmless reload)
            {
                int vn = v + 2; if (vn > VV - 1) vn = VV - 1;
                const uint4* src = gbase + (size_t)vn * (8 * NPADE);
                unsigned int d = sdst + (unsigned int)(((vi + 2) % 3) * BUFB);
                cp16(d, src);
                if (l2) cp16(d + 8192u, src + 512);
                cp_commit();
            }
            // compute v from buf[vi%3]
            unsigned int cbase = cb + (unsigned int)((vi % 3) * BUFB);
            float2 cs = scs[v];
            float t0p = fmaf(xp, cs.x, fmaf(yb, cs.y, 255.5f + (float)PADL - 0.5f));
            #pragma unroll
            for (int j = 0; j < YTN; j++) {
                float tp  = fmaf((float)j, cs.y, t0p);
                float ts  = __fadd_rn(tp, MAGICF);      // biased round(t')
                float i0f = __fadd_rn(ts, -MAGICF);     // exact i0 as float
                float w   = __fadd_rn(tp, -i0f);        // w' in [-0.5, 0.5]
                unsigned int addr = __float_as_uint(ts) * 16u + cbase;
                unsigned int ex, ey, ez, ew;
                asm("ld.shared.v4.b32 {%0,%1,%2,%3}, [%4];"
                    : "=r"(ex), "=r"(ey), "=r"(ez), "=r"(ew) : "r"(addr));
                unsigned int wb;
                asm("cvt.rn.f16x2.f32 %0, %1, %1;" : "=r"(wb) : "f"(w));   // half2(w, w)
                __half2 w2h = *(__half2*)&wb;
                __half2 v0 = __hfma2(w2h, *(__half2*)&ey, *(__half2*)&ex); // rows 0,1
                __half2 v1 = __hfma2(w2h, *(__half2*)&ew, *(__half2*)&ez); // rows 2,3
                h01[j] = __hadd2(h01[j], v0);
                h23[j] = __hadd2(h23[j], v1);
            }
        }
        // flush chunk to f32
        #pragma unroll
        for (int j = 0; j < YTN; j++) {
            acc[0][j] += __low2float(h01[j]);
            acc[1][j] += __high2float(h01[j]);
            acc[2][j] += __low2float(h23[j]);
            acc[3][j] += __high2float(h23[j]);
        }
    }
    cp_wait0();

    const float scale = (float)(PI_D / (double)VV);
    int y0 = slab * YTN;
    #pragma unroll
    for (int rr = 0; rr < RT; rr++) {
        size_t obase = (((size_t)(b * RR + rq * RT + rr)) * NPIX + y0) * NPIX + tid;
        #pragma unroll
        for (int j = 0; j < YTN; j++) {
            float val = acc[rr][j] * scale;
            out[obase + (size_t)j * NPIX] = val > 0.f ? val : 0.f;
        }
    }
}

// ---------------- launch ----------------------------------------------------------------
extern "C" void kernel_launch(void* const* d_in, const int* in_sizes, int n_in,
                              void* d_out, int out_size) {
    const float* sino = (const float*)d_in[0];
    float* out = (float*)d_out;
    (void)in_sizes; (void)n_in; (void)out_size;

    filter_kernel<<<NQUADS, 512>>>(sino);
    bp_kernel<<<BB * (RR / RT) * (NPIX / YTN), 512>>>(out);
}

// round 10
// speedup vs baseline: 1.3660x; 1.0259x over previous
#include <cuda_runtime.h>
#include <cuda_fp16.h>
#include <math.h>

// Problem constants
#define BB 2
#define VV 180
#define RR 32
#define CC 512
#define NPIX 512
#define NROWS (BB*VV*RR)        // 11520
#define NQUADS (NROWS/4)        // 2880
#define PADL 107
#define NPADE 724               // padded entries per row
#define PI_D 3.14159265358979323846
#define MAGICF 12582912.0f      // 1.5*2^23
#define KCONST 362.0f           // 255.5 + PADL - 0.5
#define BUFB  (NPADE * 16)      // bytes per row buffer

// ---------------- device globals (scratch; no runtime allocation allowed) ----------------
// quad-interleaved padded rows: 16B entry = (mid2(r0,r1), d2(r0,r1), mid2(r2,r3), d2(r2,r3))
__device__ __align__(16) uint4 g_quad[(size_t)NQUADS * NPADE];   // ~33MB

// ---------------- filter: closed-form Ram-Lak, parity-split conv, quad write -----------
__global__ void __launch_bounds__(512) filter_kernel(const float* __restrict__ sino) {
    __shared__ __align__(16) float sE[4][512];
    __shared__ __align__(16) float sO[4][512];
    __shared__ __align__(16) float sh[256];
    __shared__ __align__(16) float sF[4][512];

    int quad = blockIdx.x;
    int g   = threadIdx.x >> 7;
    int lt  = threadIdx.x & 127;

    const float4* rp = (const float4*)(sino + (size_t)(quad * 4 + g) * CC);
    float4 rv = rp[lt];
    int e0i = lt * 2;
    *(float2*)&sE[g][e0i]       = make_float2(rv.x, rv.z);
    *(float2*)&sE[g][e0i + 256] = make_float2(rv.x, rv.z);
    *(float2*)&sO[g][e0i]       = make_float2(rv.y, rv.w);
    *(float2*)&sO[g][e0i + 256] = make_float2(rv.y, rv.w);

    if (threadIdx.x < 256) {
        int k = threadIdx.x;
        float s = sinf((float)(2 * k + 1) * (float)(PI_D / 512.0));
        sh[k] = -7.62939453125e-6f / (s * s);
    }
    __syncthreads();

    int p  = lt >> 6;
    int q  = lt & 63;
    int o0 = q * 4;

    const float* part = p ? sE[g] : sO[g];
    const float* own  = p ? sO[g] : sE[g];

    float a0 = 0.f, a1 = 0.f, a2 = 0.f, a3 = 0.f;
    float4 rb = *(const float4*)&part[o0 + 256];
    if (p == 0) {
        #pragma unroll 4
        for (int k0 = 0; k0 < 256; k0 += 4) {
            float4 hv = *(const float4*)&sh[k0];
            float4 ra = *(const float4*)&part[o0 - k0 + 252];
            a0 = fmaf(hv.x, ra.w, a0); a0 = fmaf(hv.y, ra.z, a0); a0 = fmaf(hv.z, ra.y, a0); a0 = fmaf(hv.w, ra.x, a0);
            a1 = fmaf(hv.x, rb.x, a1); a1 = fmaf(hv.y, ra.w, a1); a1 = fmaf(hv.z, ra.z, a1); a1 = fmaf(hv.w, ra.y, a1);
            a2 = fmaf(hv.x, rb.y, a2); a2 = fmaf(hv.y, rb.x, a2); a2 = fmaf(hv.z, ra.w, a2); a2 = fmaf(hv.w, ra.z, a2);
            a3 = fmaf(hv.x, rb.z, a3); a3 = fmaf(hv.y, rb.y, a3); a3 = fmaf(hv.z, rb.x, a3); a3 = fmaf(hv.w, ra.w, a3);
            rb = ra;
        }
    } else {
        #pragma unroll 4
        for (int k0 = 0; k0 < 256; k0 += 4) {
            float4 hv = *(const float4*)&sh[k0];
            float4 ra = *(const float4*)&part[o0 - k0 + 252];
            a0 = fmaf(hv.x, rb.x, a0); a0 = fmaf(hv.y, ra.w, a0); a0 = fmaf(hv.z, ra.z, a0); a0 = fmaf(hv.w, ra.y, a0);
            a1 = fmaf(hv.x, rb.y, a1); a1 = fmaf(hv.y, rb.x, a1); a1 = fmaf(hv.z, ra.w, a1); a1 = fmaf(hv.w, ra.z, a1);
            a2 = fmaf(hv.x, rb.z, a2); a2 = fmaf(hv.y, rb.y, a2); a2 = fmaf(hv.z, rb.x, a2); a2 = fmaf(hv.w, ra.w, a2);
            a3 = fmaf(hv.x, rb.w, a3); a3 = fmaf(hv.y, rb.z, a3); a3 = fmaf(hv.z, rb.y, a3); a3 = fmaf(hv.w, rb.x, a3);
            rb = ra;
        }
    }
    int outbase = 2 * o0 + p;
    sF[g][outbase + 0] = fmaf(0.5f, own[o0 + 0], a0);
    sF[g][outbase + 2] = fmaf(0.5f, own[o0 + 1], a1);
    sF[g][outbase + 4] = fmaf(0.5f, own[o0 + 2], a2);
    sF[g][outbase + 6] = fmaf(0.5f, own[o0 + 3], a3);
    __syncthreads();

    uint4* dst = g_quad + (size_t)quad * NPADE;
    for (int j = threadIdx.x; j < NPADE; j += 512) {
        int ia = j - PADL;       ia = ia < 0 ? 0 : (ia > 511 ? 511 : ia);
        int ib = j - (PADL - 1); ib = ib < 0 ? 0 : (ib > 511 ? 511 : ib);
        float f0a = sF[0][ia], f0b = sF[0][ib];
        float f1a = sF[1][ia], f1b = sF[1][ib];
        float f2a = sF[2][ia], f2b = sF[2][ib];
        float f3a = sF[3][ia], f3b = sF[3][ib];
        __half2 m01 = __floats2half2_rn(0.5f * (f0a + f0b), 0.5f * (f1a + f1b));
        __half2 d01 = __floats2half2_rn(f0b - f0a, f1b - f1a);
        __half2 m23 = __floats2half2_rn(0.5f * (f2a + f2b), 0.5f * (f3a + f3b));
        __half2 d23 = __floats2half2_rn(f2b - f2a, f3b - f3a);
        uint4 e;
        e.x = *(unsigned int*)&m01; e.y = *(unsigned int*)&d01;
        e.z = *(unsigned int*)&m23; e.w = *(unsigned int*)&d23;
        dst[j] = e;
    }
}

// ---------------- cp.async helpers ------------------------------------------------------
__device__ __forceinline__ void cp16(unsigned int sdst, const void* gsrc) {
    asm volatile("cp.async.cg.shared.global [%0], [%1], 16;" :: "r"(sdst), "l"(gsrc));
}
__device__ __forceinline__ void cp_commit() { asm volatile("cp.async.commit_group;"); }
__device__ __forceinline__ void cp_wait1()  { asm volatile("cp.async.wait_group 1;"); }
__device__ __forceinline__ void cp_wait0()  { asm volatile("cp.async.wait_group 0;"); }

// ---------------- backprojection: mirror-angle shared backprojection --------------------
// 1024 blocks x 512 threads. tid = jh*256 + xh: pixel pair (xh, 511-xh), 4 y's each.
// Groups g=0..88: rows v=g+1, vm=179-g. t_vm(x) = t_v(-x) -> 4 gathers share 2 t's.
// Specials v=0, v=90 staged as group 89 and handled in a short epilogue.
__global__ void __launch_bounds__(512, 2) bp_kernel(float* __restrict__ out) {
    __shared__ __align__(16) uint4 sbuf[4][NPADE];   // 4 row buffers, 46.3KB
    __shared__ float2 scs[96];

    int tid  = threadIdx.x;
    int blk  = blockIdx.x;
    int slab = blk & 63;              // 64 slabs of 8 y
    int rq   = (blk >> 6) & 7;
    int b    = blk >> 9;

    if (tid < 90) {
        float th = (float)((double)tid * (PI_D / (double)VV));
        float s, c;
        sincosf(th, &s, &c);
        scs[tid] = make_float2(c, s);
    }

    int xh = tid & 255;
    int jh = tid >> 8;

    // staging addresses
    unsigned int sb32;
    asm("{ .reg .u64 t; cvta.to.shared.u64 t, %1; cvt.u32.u64 %0, t; }"
        : "=r"(sb32) : "l"((void*)&sbuf[0][0]));
    unsigned int cb = sb32 - 0xB4000000u;    // gather base: addr = bits(ts)*16 + cb + buf*BUFB

    const size_t rstr = (size_t)8 * NPADE;   // uint4 per row step
    const uint4* gq = g_quad + ((size_t)(b * VV) * 8 + rq) * NPADE;

    // stage rows (rA, rB) into buffer pair p (bufs 2p, 2p+1)
    auto stage = [&](int rA, int rB, int p) {
        const uint4* sA = gq + (size_t)rA * rstr;
        const uint4* sB = gq + (size_t)rB * rstr;
        unsigned int dA = sb32 + (unsigned int)(2 * p) * BUFB;
        unsigned int dB = dA + BUFB;
        cp16(dA + tid * 16u, sA + tid);
        if (tid < 212) cp16(dA + (tid + 512) * 16u, sA + tid + 512);
        else           cp16(dB + (tid - 212) * 16u, sB + (tid - 212));
        if (tid < 424) cp16(dB + (tid + 300) * 16u, sB + tid + 300);
    };

    // prologue: group0 (rows 1,179) -> pair0 ; group1 (rows 2,178) -> pair1
    stage(1, 179, 0); cp_commit();
    stage(2, 178, 1); cp_commit();

    float xp = (float)xh - 255.5f;
    float yb = (float)(slab * 8 + jh * 4) - 255.5f;

    float accA[4][4], accB[4][4];     // [r][j]
    #pragma unroll
    for (int r = 0; r < 4; r++)
        #pragma unroll
        for (int j = 0; j < 4; j++) { accA[r][j] = 0.f; accB[r][j] = 0.f; }

    __half2 hA01[4], hA23[4], hB01[4], hB23[4];
    #pragma unroll
    for (int j = 0; j < 4; j++) {
        hA01[j] = __float2half2_rn(0.f); hA23[j] = __float2half2_rn(0.f);
        hB01[j] = __float2half2_rn(0.f); hB23[j] = __float2half2_rn(0.f);
    }

    for (int g = 0; g < 89; g++) {
        cp_wait1();
        __syncthreads();

        int p = g & 1;
        unsigned int cbV  = cb + (unsigned int)(2 * p) * BUFB;
        unsigned int cbVM = cbV + BUFB;
        float2 cs = scs[g + 1];
        float u   = xp * cs.x;
        float w00 = fmaf(yb, cs.y, KCONST);

        #pragma unroll
        for (int j = 0; j < 4; j++) {
            float w0 = fmaf((float)j, cs.y, w00);
            float tA = __fadd_rn(w0, u);
            float tB = __fadd_rn(w0, -u);
            float tsA  = __fadd_rn(tA, MAGICF);
            float i0A  = __fadd_rn(tsA, -MAGICF);
            float wA   = __fadd_rn(tA, -i0A);
            float tsB  = __fadd_rn(tB, MAGICF);
            float i0B  = __fadd_rn(tsB, -MAGICF);
            float wB   = __fadd_rn(tB, -i0B);
            unsigned int aA = __float_as_uint(tsA) * 16u;
            unsigned int aB = __float_as_uint(tsB) * 16u;
            unsigned int wAb, wBb;
            asm("cvt.rn.f16x2.f32 %0, %1, %1;" : "=r"(wAb) : "f"(wA));
            asm("cvt.rn.f16x2.f32 %0, %1, %1;" : "=r"(wBb) : "f"(wB));
            __half2 wA2 = *(__half2*)&wAb, wB2 = *(__half2*)&wBb;

            unsigned int x0, x1, x2, x3;
            // row V @ tsA -> pixel A (weight wA)
            asm("ld.shared.v4.b32 {%0,%1,%2,%3}, [%4];"
                : "=r"(x0), "=r"(x1), "=r"(x2), "=r"(x3) : "r"(aA + cbV));
            hA01[j] = __hadd2(hA01[j], __hfma2(wA2, *(__half2*)&x1, *(__half2*)&x0));
            hA23[j] = __hadd2(hA23[j], __hfma2(wA2, *(__half2*)&x3, *(__half2*)&x2));
            // row V @ tsB -> pixel B (weight wB)
            asm("ld.shared.v4.b32 {%0,%1,%2,%3}, [%4];"
                : "=r"(x0), "=r"(x1), "=r"(x2), "=r"(x3) : "r"(aB + cbV));
            hB01[j] = __hadd2(hB01[j], __hfma2(wB2, *(__half2*)&x1, *(__half2*)&x0));
            hB23[j] = __hadd2(hB23[j], __hfma2(wB2, *(__half2*)&x3, *(__half2*)&x2));
            // row VM @ tsB -> pixel A (weight wB)
            asm("ld.shared.v4.b32 {%0,%1,%2,%3}, [%4];"
                : "=r"(x0), "=r"(x1), "=r"(x2), "=r"(x3) : "r"(aB + cbVM));
            hA01[j] = __hadd2(hA01[j], __hfma2(wB2, *(__half2*)&x1, *(__half2*)&x0));
            hA23[j] = __hadd2(hA23[j], __hfma2(wB2, *(__half2*)&x3, *(__half2*)&x2));
            // row VM @ tsA -> pixel B (weight wA)
            asm("ld.shared.v4.b32 {%0,%1,%2,%3}, [%4];"
                : "=r"(x0), "=r"(x1), "=r"(x2), "=r"(x3) : "r"(aA + cbVM));
            hB01[j] = __hadd2(hB01[j], __hfma2(wA2, *(__half2*)&x1, *(__half2*)&x0));
            hB23[j] = __hadd2(hB23[j], __hfma2(wA2, *(__half2*)&x3, *(__half2*)&x2));
        }

        __syncthreads();
        // stage group g+2 into pair g&1 (rows g+3, 177-g); group 89 = specials (0, 90)
        if (g + 2 <= 88)      stage(g + 3, 177 - g, p);
        else if (g + 2 == 89) stage(0, 90, p);
        cp_commit();

        // flush chunk every 4 groups
        if ((g & 3) == 3) {
            #pragma unroll
            for (int j = 0; j < 4; j++) {
                accA[0][j] += __low2float(hA01[j]);  accA[1][j] += __high2float(hA01[j]);
                accA[2][j] += __low2float(hA23[j]);  accA[3][j] += __high2float(hA23[j]);
                accB[0][j] += __low2float(hB01[j]);  accB[1][j] += __high2float(hB01[j]);
                accB[2][j] += __low2float(hB23[j]);  accB[3][j] += __high2float(hB23[j]);
                hA01[j] = __float2half2_rn(0.f); hA23[j] = __float2half2_rn(0.f);
                hB01[j] = __float2half2_rn(0.f); hB23[j] = __float2half2_rn(0.f);
            }
        }
    }

    // epilogue: specials row0 (pair 89&1=1 -> buf2) and row90 (buf3)
    cp_wait0();
    __syncthreads();
    {
        unsigned int cb0  = cb + 2u * BUFB;
        unsigned int cb90 = cb + 3u * BUFB;
        // row 0: t' = +-xp + K, y-independent
        {
            float tA = __fadd_rn(KCONST, xp);
            float tsA = __fadd_rn(tA, MAGICF);
            float wA  = __fadd_rn(tA, -__fadd_rn(tsA, -MAGICF));
            float tB = __fadd_rn(KCONST, -xp);
            float tsB = __fadd_rn(tB, MAGICF);
            float wB  = __fadd_rn(tB, -__fadd_rn(tsB, -MAGICF));
            unsigned int wAb, wBb;
            asm("cvt.rn.f16x2.f32 %0, %1, %1;" : "=r"(wAb) : "f"(wA));
            asm("cvt.rn.f16x2.f32 %0, %1, %1;" : "=r"(wBb) : "f"(wB));
            unsigned int x0, x1, x2, x3;
            asm("ld.shared.v4.b32 {%0,%1,%2,%3}, [%4];"
                : "=r"(x0), "=r"(x1), "=r"(x2), "=r"(x3) : "r"(__float_as_uint(tsA) * 16u + cb0));
            __half2 vA01 = __hfma2(*(__half2*)&wAb, *(__half2*)&x1, *(__half2*)&x0);
            __half2 vA23 = __hfma2(*(__half2*)&wAb, *(__half2*)&x3, *(__half2*)&x2);
            asm("ld.shared.v4.b32 {%0,%1,%2,%3}, [%4];"
                : "=r"(x0), "=r"(x1), "=r"(x2), "=r"(x3) : "r"(__float_as_uint(tsB) * 16u + cb0));
            __half2 vB01 = __hfma2(*(__half2*)&wBb, *(__half2*)&x1, *(__half2*)&x0);
            __half2 vB23 = __hfma2(*(__half2*)&wBb, *(__half2*)&x3, *(__half2*)&x2);
            #pragma unroll
            for (int j = 0; j < 4; j++) {
                hA01[j] = __hadd2(hA01[j], vA01); hA23[j] = __hadd2(hA23[j], vA23);
                hB01[j] = __hadd2(hB01[j], vB01); hB23[j] = __hadd2(hB23[j], vB23);
            }
        }
        // row 90: t' = yb + j + K, x-independent -> same contribution to A and B
        #pragma unroll
        for (int j = 0; j < 4; j++) {
            float t  = __fadd_rn(__fadd_rn(yb, (float)j), KCONST);
            float ts = __fadd_rn(t, MAGICF);
            float w  = __fadd_rn(t, -__fadd_rn(ts, -MAGICF));
            unsigned int wb;
            asm("cvt.rn.f16x2.f32 %0, %1, %1;" : "=r"(wb) : "f"(w));
            unsigned int x0, x1, x2, x3;
            asm("ld.shared.v4.b32 {%0,%1,%2,%3}, [%4];"
                : "=r"(x0), "=r"(x1), "=r"(x2), "=r"(x3) : "r"(__float_as_uint(ts) * 16u + cb90));
            __half2 v01 = __hfma2(*(__half2*)&wb, *(__half2*)&x1, *(__half2*)&x0);
            __half2 v23 = __hfma2(*(__half2*)&wb, *(__half2*)&x3, *(__half2*)&x2);
            hA01[j] = __hadd2(hA01[j], v01); hA23[j] = __hadd2(hA23[j], v23);
            hB01[j] = __hadd2(hB01[j], v01); hB23[j] = __hadd2(hB23[j], v23);
        }
        // final flush
        #pragma unroll
        for (int j = 0; j < 4; j++) {
            accA[0][j] += __low2float(hA01[j]);  accA[1][j] += __high2float(hA01[j]);
            accA[2][j] += __low2float(hA23[j]);  accA[3][j] += __high2float(hA23[j]);
            accB[0][j] += __low2float(hB01[j]);  accB[1][j] += __high2float(hB01[j]);
            accB[2][j] += __low2float(hB23[j]);  accB[3][j] += __high2float(hB23[j]);
        }
    }

    const float scale = (float)(PI_D / (double)VV);
    int y0 = slab * 8 + jh * 4;
    #pragma unroll
    for (int r = 0; r < 4; r++) {
        size_t obase = (((size_t)(b * RR + rq * 4 + r)) * NPIX + y0) * NPIX;
        #pragma unroll
        for (int j = 0; j < 4; j++) {
            float vA = accA[r][j] * scale;
            float vB = accB[r][j] * scale;
            out[obase + (size_t)j * NPIX + xh]         = vA > 0.f ? vA : 0.f;
            out[obase + (size_t)j * NPIX + (511 - xh)] = vB > 0.f ? vB : 0.f;
        }
    }
}

// ---------------- launch ----------------------------------------------------------------
extern "C" void kernel_launch(void* const* d_in, const int* in_sizes, int n_in,
                              void* d_out, int out_size) {
    const float* sino = (const float*)d_in[0];
    float* out = (float*)d_out;
    (void)in_sizes; (void)n_in; (void)out_size;

    filter_kernel<<<NQUADS, 512>>>(sino);
    bp_kernel<<<BB * (RR / 4) * (NPIX / 8), 512>>>(out);
}